// round 9
// baseline (speedup 1.0000x reference)
#include <cuda_runtime.h>
#include <math.h>

#define N_SZ 14000
#define H 256
#define K1 16
#define K2 32
#define KT 48
#define BN 64
#define C 7
#define PER_CLASS 2000
#define EPSC 1e-8f
#define TM 64
#define XPAD 68

// scratch (device globals: allocation-free)
__device__ float g_xin[N_SZ * H];
__device__ float g_cebuf[N_SZ * H];
__device__ float g_rawret[N_SZ * H];
__device__ float g_avesum[C * H];

__device__ __forceinline__ float dot4(float4 a, float4 b) {
    return a.x*b.x + a.y*b.y + a.z*b.z + a.w*b.w;
}

// ---------------- kernel 1: gather + cosine attention -> xin, ce ----------------
// one block per node; 256 threads = 8 warps. Warp w owns ks {w, w+8, ..., w+40}.
// Lane owns h = lane*4 and h = lane*4+128 (two float4 covering the 256-float row).
#define ATTN_SMEM_FLOATS (KT*H + 4*H + KT + KT + KT + 8 + KT)
#define ATTN_SMEM_BYTES (ATTN_SMEM_FLOATS * 4)

__global__ void __launch_bounds__(256) attn_kernel(
    const float* __restrict__ embeds, const float* __restrict__ w_self,
    const float* __restrict__ w_n, const float* __restrict__ w_n2,
    const int* __restrict__ idx, const int* __restrict__ nbr,
    const int* __restrict__ nbr2)
{
    extern __shared__ float sm[];
    float* s_nb   = sm;                    // KT*H  (48KB) weighted neighbor rows
    float* s_part = s_nb + KT*H;           // 4*H   weighted-sum partials
    float* s_dot  = s_part + 4*H;          // KT
    float* s_nrm  = s_dot + KT;            // KT
    float* s_w    = s_nrm + KT;            // KT
    float* s_cn   = s_w + KT;              // 8 (pad)
    int*   s_rows = (int*)(s_cn + 8);      // KT

    const int n = blockIdx.x;
    const int t = threadIdx.x;
    const int lane = t & 31;
    const int warp = t >> 5;

    // fold-in: zero the class-sum accumulator (blocks 0..6)
    if (n < C) g_avesum[n*H + t] = 0.f;

    if (t < KT)
        s_rows[t] = (t < K1) ? nbr[n*K1 + t] : nbr2[n*K2 + (t - K1)];

    const int center = idx[n];
    const int o0 = lane * 4;
    const int o1 = o0 + 128;

    float4 wna  = *(const float4*)(w_n  + o0), wnb  = *(const float4*)(w_n  + o1);
    float4 wn2a = *(const float4*)(w_n2 + o0), wn2b = *(const float4*)(w_n2 + o1);
    float4 wsa  = *(const float4*)(w_self + o0), wsb = *(const float4*)(w_self + o1);
    float4 ca = *(const float4*)(embeds + (size_t)center*H + o0);
    float4 cb = *(const float4*)(embeds + (size_t)center*H + o1);
    ca.x *= wsa.x; ca.y *= wsa.y; ca.z *= wsa.z; ca.w *= wsa.w;
    cb.x *= wsb.x; cb.y *= wsb.y; cb.z *= wsb.z; cb.w *= wsb.w;

    // ||ce||^2 (warp 0 covers full row)
    if (warp == 0) {
        float q = dot4(ca, ca) + dot4(cb, cb);
        #pragma unroll
        for (int o = 16; o; o >>= 1) q += __shfl_down_sync(0xffffffffu, q, o);
        if (lane == 0) s_cn[0] = q;
    }
    __syncthreads();

    // preload row ids (breaks LDS dependency out of the gather loop)
    int rows[6];
    #pragma unroll
    for (int j = 0; j < 6; j++) rows[j] = s_rows[j*8 + warp];

    #pragma unroll
    for (int j = 0; j < 6; j++) {
        const int k = j*8 + warp;
        const float* rp = embeds + (size_t)rows[j]*H;
        float4 va = *(const float4*)(rp + o0);
        float4 vb = *(const float4*)(rp + o1);
        if (j < 2) {   // k < 16 for all warps
            va.x *= wna.x; va.y *= wna.y; va.z *= wna.z; va.w *= wna.w;
            vb.x *= wnb.x; vb.y *= wnb.y; vb.z *= wnb.z; vb.w *= wnb.w;
        } else {
            va.x *= wn2a.x; va.y *= wn2a.y; va.z *= wn2a.z; va.w *= wn2a.w;
            vb.x *= wn2b.x; vb.y *= wn2b.y; vb.z *= wn2b.z; vb.w *= wn2b.w;
        }
        *(float4*)(s_nb + k*H + o0) = va;
        *(float4*)(s_nb + k*H + o1) = vb;
        float d = dot4(ca, va) + dot4(cb, vb);
        float q = dot4(va, va) + dot4(vb, vb);
        #pragma unroll
        for (int o = 16; o; o >>= 1) {
            d += __shfl_down_sync(0xffffffffu, d, o);
            q += __shfl_down_sync(0xffffffffu, q, o);
        }
        if (lane == 0) { s_dot[k] = d; s_nrm[k] = q; }
    }
    __syncthreads();

    // sims + softmax over 48 (warp 0)
    if (warp == 0) {
        const float cn = fmaxf(sqrtf(s_cn[0]), EPSC);
        float a = s_dot[lane] / (cn * fmaxf(sqrtf(s_nrm[lane]), EPSC));
        float b = (lane < 16)
                ? s_dot[32 + lane] / (cn * fmaxf(sqrtf(s_nrm[32 + lane]), EPSC))
                : -1e30f;
        float mx = fmaxf(a, b);
        #pragma unroll
        for (int o = 16; o; o >>= 1) mx = fmaxf(mx, __shfl_xor_sync(0xffffffffu, mx, o));
        float ea = __expf(a - mx);
        float eb = (lane < 16) ? __expf(b - mx) : 0.f;
        float s = ea + eb;
        #pragma unroll
        for (int o = 16; o; o >>= 1) s += __shfl_xor_sync(0xffffffffu, s, o);
        float inv = 1.f / s;
        s_w[lane] = ea * inv;
        if (lane < 16) s_w[32 + lane] = eb * inv;
    }
    __syncthreads();

    // weighted sum of neighbor rows: t -> h4=(t&63)*4, kgrp = t>>6 handles 12 ks
    const int kgrp = t >> 6;
    const int h4 = (t & 63) * 4;
    float4 p = make_float4(0.f, 0.f, 0.f, 0.f);
    #pragma unroll
    for (int j = 0; j < 12; j++) {
        int k = kgrp*12 + j;
        float wk = s_w[k];
        float4 nv = *(const float4*)(s_nb + k*H + h4);
        p.x += wk*nv.x; p.y += wk*nv.y; p.z += wk*nv.z; p.w += wk*nv.w;
    }
    *(float4*)(s_part + kgrp*H + h4) = p;
    __syncthreads();

    if (t < 64) {
        // warp0 lane l: owns h=o0=t*4 (ca); warp1 lane l: owns h=o1=128+l*4=t*4 (cb)
        float4 ce4 = (warp == 0) ? ca : cb;
        float4 r = ce4;
        #pragma unroll
        for (int g = 0; g < 4; g++) {
            float4 pp = *(const float4*)(s_part + g*H + t*4);
            r.x += pp.x; r.y += pp.y; r.z += pp.z; r.w += pp.w;
        }
        *(float4*)(g_xin   + (size_t)n*H + t*4) = r;
        *(float4*)(g_cebuf + (size_t)n*H + t*4) = ce4;
    }
}

// ---------------- kernel 2: adapter (H->B elu ->H) + rawret + class partial sums ----
// 64 nodes per block, 256 threads.
#define ADPT_SMEM_FLOATS (H*XPAD + BN*XPAD + C*H + TM)
#define ADPT_SMEM_BYTES (ADPT_SMEM_FLOATS * 4)

__global__ void __launch_bounds__(256, 2) adapter_kernel(
    const float* __restrict__ W1, const float* __restrict__ b1,
    const float* __restrict__ W2, const float* __restrict__ b2,
    const int* __restrict__ labels)
{
    extern __shared__ float sm[];
    float* xsT  = sm;                     // H*XPAD
    float* hsT  = xsT + H*XPAD;           // BN*XPAD
    float* cls  = hsT + BN*XPAD;          // C*H
    int*  s_lab = (int*)(cls + C*H);      // TM

    const int t  = threadIdx.x;
    const int m0 = blockIdx.x * TM;
    const int cnt = min(TM, N_SZ - m0);

    for (int i = t; i < C*H; i += 256) cls[i] = 0.f;
    if (t < TM) s_lab[t] = (t < cnt) ? labels[m0 + t] : 0;

    for (int i = t; i < TM*H; i += 256) {
        int m = i >> 8, h = i & 255;
        float v = (m < cnt) ? g_xin[(size_t)(m0+m)*H + h] : 0.f;
        xsT[h*XPAD + m] = v;
    }
    __syncthreads();

    // phase 1: hidden = elu(x @ W1 + b1), 4x4 register tile per thread
    {
        const int bt = t & 15;     // b0 = bt*4
        const int mt = t >> 4;     // m0r = mt*4
        float acc[16];
        #pragma unroll
        for (int i = 0; i < 16; i++) acc[i] = 0.f;
        for (int h = 0; h < H; h++) {
            float4 xv = *(const float4*)&xsT[h*XPAD + mt*4];
            float4 wv = *(const float4*)&W1[h*BN + bt*4];
            acc[0]  += xv.x*wv.x; acc[1]  += xv.x*wv.y; acc[2]  += xv.x*wv.z; acc[3]  += xv.x*wv.w;
            acc[4]  += xv.y*wv.x; acc[5]  += xv.y*wv.y; acc[6]  += xv.y*wv.z; acc[7]  += xv.y*wv.w;
            acc[8]  += xv.z*wv.x; acc[9]  += xv.z*wv.y; acc[10] += xv.z*wv.z; acc[11] += xv.z*wv.w;
            acc[12] += xv.w*wv.x; acc[13] += xv.w*wv.y; acc[14] += xv.w*wv.z; acc[15] += xv.w*wv.w;
        }
        #pragma unroll
        for (int i = 0; i < 4; i++) {
            #pragma unroll
            for (int j = 0; j < 4; j++) {
                float x = acc[i*4 + j] + b1[bt*4 + j];
                x = (x > 0.f) ? x : expm1f(x);
                hsT[(bt*4 + j)*XPAD + (mt*4 + i)] = x;
            }
        }
    }
    __syncthreads();

    // phase 2: out[m][h] = b2[h] + sum_b hsT[b][m]*W2[b][h]; thread t = h.
    // two halves of 32 m's each to keep register pressure low (no spills).
    const float bias = b2[t];
    #pragma unroll
    for (int half = 0; half < 2; half++) {
        float out[32];
        #pragma unroll
        for (int m = 0; m < 32; m++) out[m] = bias;
        for (int b = 0; b < BN; b++) {
            float w2v = W2[b*H + t];
            #pragma unroll
            for (int mq = 0; mq < 8; mq++) {
                float4 hv = *(const float4*)&hsT[b*XPAD + half*32 + mq*4];
                out[mq*4+0] += hv.x * w2v;
                out[mq*4+1] += hv.y * w2v;
                out[mq*4+2] += hv.z * w2v;
                out[mq*4+3] += hv.w * w2v;
            }
        }
        #pragma unroll
        for (int m = 0; m < 32; m++) {
            int gm = half*32 + m;
            if (gm < cnt) {
                float r = out[m] + g_cebuf[(size_t)(m0+gm)*H + t];
                g_rawret[(size_t)(m0+gm)*H + t] = r;
                cls[s_lab[gm]*H + t] += r;    // column t private per thread: no race
            }
        }
    }
    __syncthreads();
    for (int i = t; i < C*H; i += 256) atomicAdd(&g_avesum[i], cls[i]);
}

// ---------------- kernel 3: final cosine vs class means + softmax over C --------
__global__ void __launch_bounds__(256) out_kernel(float* __restrict__ ret)
{
    __shared__ float s_ave[C*H];
    __shared__ float s_rinv[C];
    const int t = threadIdx.x, warp = t >> 5, lane = t & 31;
    const int o0 = lane*4, o1 = o0 + 128;

    for (int i = t; i < C*H; i += 256) s_ave[i] = g_avesum[i] * (1.f / PER_CLASS);
    __syncthreads();
    if (warp < C) {
        float4 a = *(const float4*)(s_ave + warp*H + o0);
        float4 b = *(const float4*)(s_ave + warp*H + o1);
        float q = dot4(a, a) + dot4(b, b);
        #pragma unroll
        for (int o = 16; o; o >>= 1) q += __shfl_xor_sync(0xffffffffu, q, o);
        if (lane == 0) s_rinv[warp] = 1.f / fmaxf(sqrtf(q), EPSC);
    }
    __syncthreads();

    const int node = blockIdx.x * 8 + warp;
    if (node < N_SZ) {
        float4 r0 = *(const float4*)(g_rawret + (size_t)node*H + o0);
        float4 r1 = *(const float4*)(g_rawret + (size_t)node*H + o1);
        float sn = dot4(r0, r0) + dot4(r1, r1);
        #pragma unroll
        for (int o = 16; o; o >>= 1) sn += __shfl_xor_sync(0xffffffffu, sn, o);
        float rin = 1.f / fmaxf(sqrtf(sn), EPSC);

        float cosv[C];
        #pragma unroll
        for (int c = 0; c < C; c++) {
            float4 a = *(const float4*)(s_ave + c*H + o0);
            float4 b = *(const float4*)(s_ave + c*H + o1);
            float d = dot4(r0, a) + dot4(r1, b);
            #pragma unroll
            for (int o = 16; o; o >>= 1) d += __shfl_xor_sync(0xffffffffu, d, o);
            cosv[c] = d * rin * s_rinv[c];
        }
        float mx = cosv[0];
        #pragma unroll
        for (int c = 1; c < C; c++) mx = fmaxf(mx, cosv[c]);
        float e[C]; float s = 0.f;
        #pragma unroll
        for (int c = 0; c < C; c++) { e[c] = __expf(cosv[c] - mx); s += e[c]; }
        float inv = 1.f / s;
        if (lane == 0) {
            #pragma unroll
            for (int c = 0; c < C; c++) ret[node*C + c] = e[c] * inv;
        }
    }
}

// ---------------- launch ----------------
extern "C" void kernel_launch(void* const* d_in, const int* in_sizes, int n_in,
                              void* d_out, int out_size)
{
    const float* embeds = (const float*)d_in[0];
    const float* w_self = (const float*)d_in[1];
    const float* w_n    = (const float*)d_in[2];
    const float* w_n2   = (const float*)d_in[3];
    const float* W1     = (const float*)d_in[4];
    const float* b1     = (const float*)d_in[5];
    const float* W2     = (const float*)d_in[6];
    const float* b2     = (const float*)d_in[7];
    const int*   idx    = (const int*)d_in[8];
    const int*   nbr    = (const int*)d_in[9];
    const int*   nbr2   = (const int*)d_in[10];
    const int*   labels = (const int*)d_in[11];
    float* ret = (float*)d_out;

    cudaFuncSetAttribute(attn_kernel, cudaFuncAttributeMaxDynamicSharedMemorySize, ATTN_SMEM_BYTES);
    cudaFuncSetAttribute(adapter_kernel, cudaFuncAttributeMaxDynamicSharedMemorySize, ADPT_SMEM_BYTES);

    attn_kernel<<<N_SZ, 256, ATTN_SMEM_BYTES>>>(embeds, w_self, w_n, w_n2, idx, nbr, nbr2);
    adapter_kernel<<<(N_SZ + TM - 1)/TM, 256, ADPT_SMEM_BYTES>>>(W1, b1, W2, b2, labels);
    out_kernel<<<(N_SZ + 7)/8, 256>>>(ret);
}

// round 12
// speedup vs baseline: 1.0074x; 1.0074x over previous
#include <cuda_runtime.h>
#include <math.h>

#define N_SZ 14000
#define H 256
#define K1 16
#define K2 32
#define KT 48
#define BN 64
#define C 7
#define PER_CLASS 2000
#define EPSC 1e-8f
#define TM 64
#define XPAD 68

// scratch (device globals: allocation-free)
__device__ float g_xin[N_SZ * H];
__device__ float g_cebuf[N_SZ * H];
__device__ float g_rawret[N_SZ * H];
__device__ float g_avesum[C * H];

__device__ __forceinline__ float dot4(float4 a, float4 b) {
    return a.x*b.x + a.y*b.y + a.z*b.z + a.w*b.w;
}

// ---------------- kernel 1: gather + cosine attention -> xin, ce ----------------
// one block per node; 256 threads = 8 warps. Warp w owns ks {w, w+8, ..., w+40}.
// Lane owns h = lane*4 and h = lane*4+128 (two float4 covering the 256-float row).
#define ATTN_SMEM_FLOATS (KT*H + 4*H + KT + KT + KT + 8 + KT)
#define ATTN_SMEM_BYTES (ATTN_SMEM_FLOATS * 4)

__global__ void __launch_bounds__(256) attn_kernel(
    const float* __restrict__ embeds, const float* __restrict__ w_self,
    const float* __restrict__ w_n, const float* __restrict__ w_n2,
    const int* __restrict__ idx, const int* __restrict__ nbr,
    const int* __restrict__ nbr2)
{
    extern __shared__ float sm[];
    float* s_nb   = sm;                    // KT*H  (48KB) weighted neighbor rows
    float* s_part = s_nb + KT*H;           // 4*H   weighted-sum partials
    float* s_dot  = s_part + 4*H;          // KT
    float* s_nrm  = s_dot + KT;            // KT
    float* s_w    = s_nrm + KT;            // KT
    float* s_cn   = s_w + KT;              // 8 (pad)
    int*   s_rows = (int*)(s_cn + 8);      // KT

    const int n = blockIdx.x;
    const int t = threadIdx.x;
    const int lane = t & 31;
    const int warp = t >> 5;

    // fold-in: zero the class-sum accumulator (blocks 0..6)
    if (n < C) g_avesum[n*H + t] = 0.f;

    if (t < KT)
        s_rows[t] = (t < K1) ? nbr[n*K1 + t] : nbr2[n*K2 + (t - K1)];

    const int center = idx[n];
    const int o0 = lane * 4;
    const int o1 = o0 + 128;

    float4 wna  = *(const float4*)(w_n  + o0), wnb  = *(const float4*)(w_n  + o1);
    float4 wn2a = *(const float4*)(w_n2 + o0), wn2b = *(const float4*)(w_n2 + o1);
    float4 wsa  = *(const float4*)(w_self + o0), wsb = *(const float4*)(w_self + o1);
    float4 ca = *(const float4*)(embeds + (size_t)center*H + o0);
    float4 cb = *(const float4*)(embeds + (size_t)center*H + o1);
    ca.x *= wsa.x; ca.y *= wsa.y; ca.z *= wsa.z; ca.w *= wsa.w;
    cb.x *= wsb.x; cb.y *= wsb.y; cb.z *= wsb.z; cb.w *= wsb.w;

    // ||ce||^2 (warp 0 covers full row)
    if (warp == 0) {
        float q = dot4(ca, ca) + dot4(cb, cb);
        #pragma unroll
        for (int o = 16; o; o >>= 1) q += __shfl_down_sync(0xffffffffu, q, o);
        if (lane == 0) s_cn[0] = q;
    }
    __syncthreads();

    // preload row ids (breaks LDS dependency out of the gather loop)
    int rows[6];
    #pragma unroll
    for (int j = 0; j < 6; j++) rows[j] = s_rows[j*8 + warp];

    #pragma unroll
    for (int j = 0; j < 6; j++) {
        const int k = j*8 + warp;
        const float* rp = embeds + (size_t)rows[j]*H;
        float4 va = *(const float4*)(rp + o0);
        float4 vb = *(const float4*)(rp + o1);
        if (j < 2) {   // k < 16 for all warps
            va.x *= wna.x; va.y *= wna.y; va.z *= wna.z; va.w *= wna.w;
            vb.x *= wnb.x; vb.y *= wnb.y; vb.z *= wnb.z; vb.w *= wnb.w;
        } else {
            va.x *= wn2a.x; va.y *= wn2a.y; va.z *= wn2a.z; va.w *= wn2a.w;
            vb.x *= wn2b.x; vb.y *= wn2b.y; vb.z *= wn2b.z; vb.w *= wn2b.w;
        }
        *(float4*)(s_nb + k*H + o0) = va;
        *(float4*)(s_nb + k*H + o1) = vb;
        float d = dot4(ca, va) + dot4(cb, vb);
        float q = dot4(va, va) + dot4(vb, vb);
        #pragma unroll
        for (int o = 16; o; o >>= 1) {
            d += __shfl_down_sync(0xffffffffu, d, o);
            q += __shfl_down_sync(0xffffffffu, q, o);
        }
        if (lane == 0) { s_dot[k] = d; s_nrm[k] = q; }
    }
    __syncthreads();

    // sims + softmax over 48 (warp 0)
    if (warp == 0) {
        const float cn = fmaxf(sqrtf(s_cn[0]), EPSC);
        float a = s_dot[lane] / (cn * fmaxf(sqrtf(s_nrm[lane]), EPSC));
        float b = (lane < 16)
                ? s_dot[32 + lane] / (cn * fmaxf(sqrtf(s_nrm[32 + lane]), EPSC))
                : -1e30f;
        float mx = fmaxf(a, b);
        #pragma unroll
        for (int o = 16; o; o >>= 1) mx = fmaxf(mx, __shfl_xor_sync(0xffffffffu, mx, o));
        float ea = __expf(a - mx);
        float eb = (lane < 16) ? __expf(b - mx) : 0.f;
        float s = ea + eb;
        #pragma unroll
        for (int o = 16; o; o >>= 1) s += __shfl_xor_sync(0xffffffffu, s, o);
        float inv = 1.f / s;
        s_w[lane] = ea * inv;
        if (lane < 16) s_w[32 + lane] = eb * inv;
    }
    __syncthreads();

    // weighted sum of neighbor rows: t -> h4=(t&63)*4, kgrp = t>>6 handles 12 ks
    const int kgrp = t >> 6;
    const int h4 = (t & 63) * 4;
    float4 p = make_float4(0.f, 0.f, 0.f, 0.f);
    #pragma unroll
    for (int j = 0; j < 12; j++) {
        int k = kgrp*12 + j;
        float wk = s_w[k];
        float4 nv = *(const float4*)(s_nb + k*H + h4);
        p.x += wk*nv.x; p.y += wk*nv.y; p.z += wk*nv.z; p.w += wk*nv.w;
    }
    *(float4*)(s_part + kgrp*H + h4) = p;
    __syncthreads();

    if (t < 64) {
        // warp0 lane l: owns h=o0=t*4 (ca); warp1 lane l: owns h=o1=128+l*4=t*4 (cb)
        float4 ce4 = (warp == 0) ? ca : cb;
        float4 r = ce4;
        #pragma unroll
        for (int g = 0; g < 4; g++) {
            float4 pp = *(const float4*)(s_part + g*H + t*4);
            r.x += pp.x; r.y += pp.y; r.z += pp.z; r.w += pp.w;
        }
        *(float4*)(g_xin   + (size_t)n*H + t*4) = r;
        *(float4*)(g_cebuf + (size_t)n*H + t*4) = ce4;
    }
}

// ---------------- kernel 2: adapter (H->B elu ->H) + rawret + class partial sums ----
// 64 nodes per block, 256 threads.
#define ADPT_SMEM_FLOATS (H*XPAD + BN*XPAD + C*H + TM)
#define ADPT_SMEM_BYTES (ADPT_SMEM_FLOATS * 4)

__global__ void __launch_bounds__(256, 2) adapter_kernel(
    const float* __restrict__ W1, const float* __restrict__ b1,
    const float* __restrict__ W2, const float* __restrict__ b2,
    const int* __restrict__ labels)
{
    extern __shared__ float sm[];
    float* xsT  = sm;                     // H*XPAD
    float* hsT  = xsT + H*XPAD;           // BN*XPAD
    float* cls  = hsT + BN*XPAD;          // C*H
    int*  s_lab = (int*)(cls + C*H);      // TM

    const int t  = threadIdx.x;
    const int m0 = blockIdx.x * TM;
    const int cnt = min(TM, N_SZ - m0);

    for (int i = t; i < C*H; i += 256) cls[i] = 0.f;
    if (t < TM) s_lab[t] = (t < cnt) ? labels[m0 + t] : 0;

    for (int i = t; i < TM*H; i += 256) {
        int m = i >> 8, h = i & 255;
        float v = (m < cnt) ? g_xin[(size_t)(m0+m)*H + h] : 0.f;
        xsT[h*XPAD + m] = v;
    }
    __syncthreads();

    // phase 1: hidden = elu(x @ W1 + b1), 4x4 register tile per thread
    {
        const int bt = t & 15;     // b0 = bt*4
        const int mt = t >> 4;     // m0r = mt*4
        float acc[16];
        #pragma unroll
        for (int i = 0; i < 16; i++) acc[i] = 0.f;
        for (int h = 0; h < H; h++) {
            float4 xv = *(const float4*)&xsT[h*XPAD + mt*4];
            float4 wv = *(const float4*)&W1[h*BN + bt*4];
            acc[0]  += xv.x*wv.x; acc[1]  += xv.x*wv.y; acc[2]  += xv.x*wv.z; acc[3]  += xv.x*wv.w;
            acc[4]  += xv.y*wv.x; acc[5]  += xv.y*wv.y; acc[6]  += xv.y*wv.z; acc[7]  += xv.y*wv.w;
            acc[8]  += xv.z*wv.x; acc[9]  += xv.z*wv.y; acc[10] += xv.z*wv.z; acc[11] += xv.z*wv.w;
            acc[12] += xv.w*wv.x; acc[13] += xv.w*wv.y; acc[14] += xv.w*wv.z; acc[15] += xv.w*wv.w;
        }
        #pragma unroll
        for (int i = 0; i < 4; i++) {
            #pragma unroll
            for (int j = 0; j < 4; j++) {
                float x = acc[i*4 + j] + b1[bt*4 + j];
                x = (x > 0.f) ? x : expm1f(x);
                hsT[(bt*4 + j)*XPAD + (mt*4 + i)] = x;
            }
        }
    }
    __syncthreads();

    // phase 2: out[m][h] = b2[h] + sum_b hsT[b][m]*W2[b][h]; thread t = h.
    // two halves of 32 m's each to keep register pressure low (no spills).
    const float bias = b2[t];
    #pragma unroll
    for (int half = 0; half < 2; half++) {
        float out[32];
        #pragma unroll
        for (int m = 0; m < 32; m++) out[m] = bias;
        for (int b = 0; b < BN; b++) {
            float w2v = W2[b*H + t];
            #pragma unroll
            for (int mq = 0; mq < 8; mq++) {
                float4 hv = *(const float4*)&hsT[b*XPAD + half*32 + mq*4];
                out[mq*4+0] += hv.x * w2v;
                out[mq*4+1] += hv.y * w2v;
                out[mq*4+2] += hv.z * w2v;
                out[mq*4+3] += hv.w * w2v;
            }
        }
        #pragma unroll
        for (int m = 0; m < 32; m++) {
            int gm = half*32 + m;
            if (gm < cnt) {
                float r = out[m] + g_cebuf[(size_t)(m0+gm)*H + t];
                g_rawret[(size_t)(m0+gm)*H + t] = r;
                cls[s_lab[gm]*H + t] += r;    // column t private per thread: no race
            }
        }
    }
    __syncthreads();
    for (int i = t; i < C*H; i += 256) atomicAdd(&g_avesum[i], cls[i]);
}

// ---------------- kernel 3: final cosine vs class means + softmax over C --------
__global__ void __launch_bounds__(256) out_kernel(float* __restrict__ ret)
{
    __shared__ float s_ave[C*H];
    __shared__ float s_rinv[C];
    const int t = threadIdx.x, warp = t >> 5, lane = t & 31;
    const int o0 = lane*4, o1 = o0 + 128;

    for (int i = t; i < C*H; i += 256) s_ave[i] = g_avesum[i] * (1.f / PER_CLASS);
    __syncthreads();
    if (warp < C) {
        float4 a = *(const float4*)(s_ave + warp*H + o0);
        float4 b = *(const float4*)(s_ave + warp*H + o1);
        float q = dot4(a, a) + dot4(b, b);
        #pragma unroll
        for (int o = 16; o; o >>= 1) q += __shfl_xor_sync(0xffffffffu, q, o);
        if (lane == 0) s_rinv[warp] = 1.f / fmaxf(sqrtf(q), EPSC);
    }
    __syncthreads();

    const int node = blockIdx.x * 8 + warp;
    if (node < N_SZ) {
        float4 r0 = *(const float4*)(g_rawret + (size_t)node*H + o0);
        float4 r1 = *(const float4*)(g_rawret + (size_t)node*H + o1);
        float sn = dot4(r0, r0) + dot4(r1, r1);
        #pragma unroll
        for (int o = 16; o; o >>= 1) sn += __shfl_xor_sync(0xffffffffu, sn, o);
        float rin = 1.f / fmaxf(sqrtf(sn), EPSC);

        float cosv[C];
        #pragma unroll
        for (int c = 0; c < C; c++) {
            float4 a = *(const float4*)(s_ave + c*H + o0);
            float4 b = *(const float4*)(s_ave + c*H + o1);
            float d = dot4(r0, a) + dot4(r1, b);
            #pragma unroll
            for (int o = 16; o; o >>= 1) d += __shfl_xor_sync(0xffffffffu, d, o);
            cosv[c] = d * rin * s_rinv[c];
        }
        float mx = cosv[0];
        #pragma unroll
        for (int c = 1; c < C; c++) mx = fmaxf(mx, cosv[c]);
        float e[C]; float s = 0.f;
        #pragma unroll
        for (int c = 0; c < C; c++) { e[c] = __expf(cosv[c] - mx); s += e[c]; }
        float inv = 1.f / s;
        if (lane == 0) {
            #pragma unroll
            for (int c = 0; c < C; c++) ret[node*C + c] = e[c] * inv;
        }
    }
}

// ---------------- launch ----------------
extern "C" void kernel_launch(void* const* d_in, const int* in_sizes, int n_in,
                              void* d_out, int out_size)
{
    const float* embeds = (const float*)d_in[0];
    const float* w_self = (const float*)d_in[1];
    const float* w_n    = (const float*)d_in[2];
    const float* w_n2   = (const float*)d_in[3];
    const float* W1     = (const float*)d_in[4];
    const float* b1     = (const float*)d_in[5];
    const float* W2     = (const float*)d_in[6];
    const float* b2     = (const float*)d_in[7];
    const int*   idx    = (const int*)d_in[8];
    const int*   nbr    = (const int*)d_in[9];
    const int*   nbr2   = (const int*)d_in[10];
    const int*   labels = (const int*)d_in[11];
    float* ret = (float*)d_out;

    cudaFuncSetAttribute(attn_kernel, cudaFuncAttributeMaxDynamicSharedMemorySize, ATTN_SMEM_BYTES);
    cudaFuncSetAttribute(adapter_kernel, cudaFuncAttributeMaxDynamicSharedMemorySize, ADPT_SMEM_BYTES);

    attn_kernel<<<N_SZ, 256, ATTN_SMEM_BYTES>>>(embeds, w_self, w_n, w_n2, idx, nbr, nbr2);
    adapter_kernel<<<(N_SZ + TM - 1)/TM, 256, ADPT_SMEM_BYTES>>>(W1, b1, W2, b2, labels);
    out_kernel<<<(N_SZ + 7)/8, 256>>>(ret);
}